// round 16
// baseline (speedup 1.0000x reference)
#include <cuda_runtime.h>
#include <cuda_bf16.h>
#include <cstdint>

#define B_    4
#define SEQ_  4096
#define D_    64
#define V_    512
#define BS_   32
#define R_    128          // SEQ/BS
#define PPB_  8256         // panels per batch = R(R+1)/2
#define PAD   72           // bf16 row pitch (144B): 16B-aligned, conflict-free

// Scratch for fallback path only
__device__ float g_scores[(size_t)B_ * SEQ_ * V_];              // [b][m][v]

#define MMA_BF16(c, a, b)                                                     \
    asm volatile(                                                             \
        "mma.sync.aligned.m16n8k16.row.col.f32.bf16.bf16.f32 "               \
        "{%0,%1,%2,%3}, {%4,%5,%6,%7}, {%8,%9}, {%0,%1,%2,%3};"              \
        : "+f"((c)[0]), "+f"((c)[1]), "+f"((c)[2]), "+f"((c)[3])              \
        : "r"((a)[0]), "r"((a)[1]), "r"((a)[2]), "r"((a)[3]),                 \
          "r"((b)[0]), "r"((b)[1]))

#define LDSM_X4(r, addr)                                                      \
    asm volatile("ldmatrix.sync.aligned.m8n8.x4.shared.b16 {%0,%1,%2,%3}, [%4];" \
                 : "=r"((r)[0]), "=r"((r)[1]), "=r"((r)[2]), "=r"((r)[3])     \
                 : "r"(addr))

#define LDSM_X2(r, addr)                                                      \
    asm volatile("ldmatrix.sync.aligned.m8n8.x2.shared.b16 {%0,%1}, [%2];"    \
                 : "=r"((r)[0]), "=r"((r)[1])                                 \
                 : "r"(addr))

// Split a float4 into hi/lo bf16 packs (4 bf16 = 8 bytes each).
__device__ __forceinline__ void split4(float4 x, uint2& h, uint2& l) {
    __nv_bfloat162 h01 = __floats2bfloat162_rn(x.x, x.y);
    __nv_bfloat162 h23 = __floats2bfloat162_rn(x.z, x.w);
    __nv_bfloat162 l01 = __floats2bfloat162_rn(x.x - __low2float(h01),
                                               x.y - __high2float(h01));
    __nv_bfloat162 l23 = __floats2bfloat162_rn(x.z - __low2float(h23),
                                               x.w - __high2float(h23));
    h.x = *(unsigned*)&h01; h.y = *(unsigned*)&h23;
    l.x = *(unsigned*)&l01; l.y = *(unsigned*)&l23;
}

// SMEM layout (bytes) for the fused run kernel
#define SM_PANEL 0                       // 32 x 512 fp32 = 65536
#define SM_AHI   65536                   // 32 x PAD bf16 = 4608
#define SM_ALO   (65536 + 4608)
#define SM_EHI   (65536 + 9216)          // 128 x PAD bf16 = 18432
#define SM_ELO   (65536 + 9216 + 18432)
#define SM_TOTAL (65536 + 9216 + 36864)  // 111616 B (= 109 KB)

// ---------------------------------------------------------------------------
// FUSED run kernel: one CTA per (b, rb) run. Phase 1 computes the run's
// 32x512 score panel (q rows @ emb^T, bf16-split: hi*hi + hi*lo + lo*hi)
// directly into smem, streaming emb through a 128-row tile buffer (4 steps).
// Phase 2 gathers all rb+1 panels of the run from the smem panel.
// Total MMA count across the grid equals the standalone GEMM (each panel
// computed exactly once). No inter-CTA synchronization. 2 CTAs/SM.
// ---------------------------------------------------------------------------
__global__ __launch_bounds__(1024, 2) void fused_run_kernel(
    const float* __restrict__ q, const float* __restrict__ emb,
    const int* __restrict__ info,
    const int* __restrict__ idxs_batch,
    const int* __restrict__ idxs_row,
    float* __restrict__ out) {
    extern __shared__ char smraw[];
    float* panel = (float*)(smraw + SM_PANEL);            // [32][512]
    __nv_bfloat16* a_hi = (__nv_bfloat16*)(smraw + SM_AHI);
    __nv_bfloat16* a_lo = (__nv_bfloat16*)(smraw + SM_ALO);
    __nv_bfloat16* e_hi = (__nv_bfloat16*)(smraw + SM_EHI);
    __nv_bfloat16* e_lo = (__nv_bfloat16*)(smraw + SM_ELO);

    // Largest runs first: rb descending
    const int bi = blockIdx.x & 3;
    const int rb_idx = (R_ - 1) - (blockIdx.x >> 2);
    const int p_start = bi * PPB_ + (rb_idx * (rb_idx + 1)) / 2;
    const int count = rb_idx + 1;

    const int b  = __ldg(&idxs_batch[p_start]);
    const int rb = __ldg(&idxs_row[p_start]);

    const int tid = threadIdx.x;

    // ---- Gather-phase index prefetch (independent of panel) ----
    const int sub = tid >> 8;      // 0..3: which of 4 panels per iteration
    const int t   = tid & 255;     // int4 position within panel
    const int4* __restrict__ ip = (const int4*)info;
    int4 idx0, idx1;
    if (sub < count)
        idx0 = __ldcs(&ip[(size_t)(p_start + sub) * 256 + t]);
    if (sub + 4 < count)
        idx1 = __ldcs(&ip[(size_t)(p_start + sub + 4) * 256 + t]);

    // ---- Stage A: q rows [rb*32, rb*32+32) x 64 fp32 -> hi/lo bf16 ----
    const float4* __restrict__ qsrc =
        (const float4*)(q + ((size_t)b * SEQ_ + rb * BS_) * D_);
    if (tid < 512) {               // 32 rows x 16 float4
        int r = tid >> 4, c4 = (tid & 15) * 4;
        uint2 h, l;
        split4(qsrc[tid], h, l);
        *(uint2*)&a_hi[r * PAD + c4] = h;
        *(uint2*)&a_lo[r * PAD + c4] = l;
    }

    // ---- Phase 1: compute panel in 4 n-tiles of 128 emb rows ----
    const int wid = tid >> 5, lane = tid & 31;
    const int mi  = wid & 1;       // m-tile: rows mi*16 .. +16
    const int niw = wid >> 1;      // 0..15: n8-tile within the 128-wide tile
    const int g  = lane >> 2;
    const int t4 = lane & 3;

    const uint32_t aHiB = (uint32_t)__cvta_generic_to_shared(a_hi);
    const uint32_t aLoB = (uint32_t)__cvta_generic_to_shared(a_lo);
    const uint32_t eHiB = (uint32_t)__cvta_generic_to_shared(e_hi);
    const uint32_t eLoB = (uint32_t)__cvta_generic_to_shared(e_lo);
    const int asub = lane >> 3;
    const int alrow = lane & 7;
    const uint32_t aLaneOff =
        (uint32_t)((((asub & 1) * 8 + alrow) * PAD + (asub >> 1) * 8) * 2);
    const int bl = lane & 15;
    const uint32_t bLaneOff =
        (uint32_t)(((bl & 7) * PAD + (bl >> 3) * 8) * 2);
    const uint32_t aTileBase = (uint32_t)((mi * 16) * PAD * 2) + aLaneOff;
    const uint32_t bTileBase = (uint32_t)((niw * 8) * PAD * 2) + bLaneOff;

#pragma unroll
    for (int nt = 0; nt < 4; ++nt) {
        __syncthreads();           // previous tile's MMA reads done
        // stage emb rows [nt*128, +128): 2048 float4 over 1024 threads
        const float4* __restrict__ esrc =
            (const float4*)(emb + ((size_t)b * V_ + nt * 128) * D_);
#pragma unroll
        for (int j = 0; j < 2; ++j) {
            int idx = tid + j * 1024;
            int r = idx >> 4, c4 = (idx & 15) * 4;
            uint2 h, l;
            split4(esrc[idx], h, l);
            *(uint2*)&e_hi[r * PAD + c4] = h;
            *(uint2*)&e_lo[r * PAD + c4] = l;
        }
        __syncthreads();

        float c[4] = {0.f, 0.f, 0.f, 0.f};
#pragma unroll
        for (int ks = 0; ks < 4; ++ks) {
            const uint32_t kOff = (uint32_t)(ks * 16 * 2);
            unsigned ahi[4], alo[4], bhi[2], blo[2];
            LDSM_X4(ahi, aHiB + aTileBase + kOff);
            LDSM_X4(alo, aLoB + aTileBase + kOff);
            LDSM_X2(bhi, eHiB + bTileBase + kOff);
            LDSM_X2(blo, eLoB + bTileBase + kOff);
            MMA_BF16(c, ahi, bhi);
            MMA_BF16(c, ahi, blo);
            MMA_BF16(c, alo, bhi);
        }
        // write fragment to smem panel
        const int row0 = mi * 16 + g;
        const int col = nt * 128 + niw * 8 + 2 * t4;
        *(float2*)&panel[row0 * V_ + col] = make_float2(c[0], c[1]);
        *(float2*)&panel[(row0 + 8) * V_ + col] = make_float2(c[2], c[3]);
    }
    __syncthreads();               // panel complete

    // ---- Phase 2: gather all panels of this run from the smem panel ----
    const float* srow = panel + (t >> 3) * V_;
    for (int pp = 0; pp < count; pp += 4) {
        const int pcur = pp + sub;
        int4 idx2;
        if (pcur + 8 < count)
            idx2 = __ldcs(&ip[(size_t)(p_start + pcur + 8) * 256 + t]);

        if (pcur < count) {
            float4 o;
            o.x = srow[idx0.x];
            o.y = srow[idx0.y];
            o.z = srow[idx0.z];
            o.w = srow[idx0.w];
            __stcs(&((float4*)out)[(size_t)(p_start + pcur) * 256 + t], o);
        }
        idx0 = idx1;
        idx1 = idx2;
    }
}

// ---------------------------------------------------------------------------
// Fallback path (any P / structure): round-13 GEMM + generic gather.
// ---------------------------------------------------------------------------
__global__ __launch_bounds__(256, 2) void gemm_fallback_kernel(
    const float* __restrict__ q, const float* __restrict__ emb) {
    extern __shared__ __nv_bfloat16 sm[];
    __nv_bfloat16* a_hi = sm;
    __nv_bfloat16* a_lo = a_hi + 128 * PAD;
    __nv_bfloat16* b_hi = a_lo + 128 * PAD;
    __nv_bfloat16* b_lo = b_hi + 256 * PAD;

    const int b = blockIdx.z;
    const int mBase = blockIdx.x * 128;
    const int vBase = blockIdx.y * 256;
    const int tid = threadIdx.x;

    const float4* __restrict__ qsrc =
        (const float4*)(q + ((size_t)b * SEQ_ + mBase) * D_);
#pragma unroll
    for (int i = 0; i < 8; ++i) {
        int idx = tid + i * 256;
        int r = idx >> 4, c4 = (idx & 15) * 4;
        uint2 h, l;
        split4(qsrc[idx], h, l);
        *(uint2*)&a_hi[r * PAD + c4] = h;
        *(uint2*)&a_lo[r * PAD + c4] = l;
    }
    const float4* __restrict__ esrc =
        (const float4*)(emb + ((size_t)b * V_ + vBase) * D_);
#pragma unroll
    for (int i = 0; i < 16; ++i) {
        int idx = tid + i * 256;
        int r = idx >> 4, c4 = (idx & 15) * 4;
        uint2 h, l;
        split4(esrc[idx], h, l);
        *(uint2*)&b_hi[r * PAD + c4] = h;
        *(uint2*)&b_lo[r * PAD + c4] = l;
    }
    __syncthreads();

    const int wid = tid >> 5, lane = tid & 31;
    const int wm = wid & 3;
    const int wv = wid >> 2;
    const int g = lane >> 2;
    const int t4 = lane & 3;

    const uint32_t aHiB = (uint32_t)__cvta_generic_to_shared(a_hi);
    const uint32_t aLoB = (uint32_t)__cvta_generic_to_shared(a_lo);
    const uint32_t bHiB = (uint32_t)__cvta_generic_to_shared(b_hi);
    const uint32_t bLoB = (uint32_t)__cvta_generic_to_shared(b_lo);
    const int asub = lane >> 3;
    const int alrow = lane & 7;
    const uint32_t aLaneOff =
        (uint32_t)((((asub & 1) * 8 + alrow) * PAD + (asub >> 1) * 8) * 2);
    const int bl = lane & 15;
    const uint32_t bLaneOff =
        (uint32_t)(((bl & 7) * PAD + (bl >> 3) * 8) * 2);

#pragma unroll
    for (int vc = 0; vc < 2; ++vc) {
        float c[2][8][4];
#pragma unroll
        for (int mi = 0; mi < 2; ++mi)
#pragma unroll
            for (int ni = 0; ni < 8; ++ni)
#pragma unroll
                for (int u = 0; u < 4; ++u) c[mi][ni][u] = 0.0f;

#pragma unroll
        for (int ks = 0; ks < 4; ++ks) {
            unsigned ahi[2][4], alo[2][4];
#pragma unroll
            for (int mi = 0; mi < 2; ++mi) {
                uint32_t tileOff =
                    (uint32_t)(((wm * 32 + mi * 16) * PAD + ks * 16) * 2);
                LDSM_X4(ahi[mi], aHiB + tileOff + aLaneOff);
                LDSM_X4(alo[mi], aLoB + tileOff + aLaneOff);
            }
#pragma unroll
            for (int ni = 0; ni < 8; ++ni) {
                uint32_t nOff = (uint32_t)(
                    ((wv * 128 + vc * 64 + ni * 8) * PAD + ks * 16) * 2);
                unsigned bhi[2], blo[2];
                LDSM_X2(bhi, bHiB + nOff + bLaneOff);
                LDSM_X2(blo, bLoB + nOff + bLaneOff);
#pragma unroll
                for (int mi = 0; mi < 2; ++mi) {
                    MMA_BF16(c[mi][ni], ahi[mi], bhi);
                    MMA_BF16(c[mi][ni], ahi[mi], blo);
                    MMA_BF16(c[mi][ni], alo[mi], bhi);
                }
            }
        }
#pragma unroll
        for (int mi = 0; mi < 2; ++mi) {
#pragma unroll
            for (int ni = 0; ni < 8; ++ni) {
                int r0 = mBase + wm * 32 + mi * 16 + g;
                int col = vBase + wv * 128 + vc * 64 + ni * 8 + 2 * t4;
                float* dst = g_scores + ((size_t)b * SEQ_ + r0) * V_ + col;
                *(float2*)dst = make_float2(c[mi][ni][0], c[mi][ni][1]);
                *(float2*)(dst + 8 * V_) = make_float2(c[mi][ni][2], c[mi][ni][3]);
            }
        }
    }
}

__global__ __launch_bounds__(256) void gather_fallback_kernel(
    const int* __restrict__ info,
    const int* __restrict__ idxs_batch,
    const int* __restrict__ idxs_row,
    float* __restrict__ out,
    int P) {
    extern __shared__ float s[];
    const int p0 = blockIdx.x * 16;
    if (p0 >= P) return;
    const int pend = min(p0 + 16, P);
    const int tid = threadIdx.x;
    const float* srow = s + (tid >> 3) * V_;

    int cached = -1;
    int4 idx = ((const int4*)(info + (size_t)p0 * 1024))[tid];
    for (int p = p0; p < pend; ++p) {
        int4 idx_next;
        if (p + 1 < pend)
            idx_next = ((const int4*)(info + (size_t)(p + 1) * 1024))[tid];
        const int b  = __ldg(&idxs_batch[p]);
        const int rb = __ldg(&idxs_row[p]);
        const int key = (b << 16) | rb;
        if (key != cached) {
            __syncthreads();
            const float4* __restrict__ src = (const float4*)(
                g_scores + ((size_t)b * SEQ_ + rb * BS_) * V_);
            float4* dst = (float4*)s;
#pragma unroll
            for (int t2 = 0; t2 < 16; ++t2)
                dst[tid + t2 * 256] = src[tid + t2 * 256];
            cached = key;
            __syncthreads();
        }
        float4 o;
        o.x = srow[idx.x];
        o.y = srow[idx.y];
        o.z = srow[idx.z];
        o.w = srow[idx.w];
        ((float4*)(out + (size_t)p * 1024))[tid] = o;
        idx = idx_next;
    }
}

// ---------------------------------------------------------------------------
extern "C" void kernel_launch(void* const* d_in, const int* in_sizes, int n_in,
                              void* d_out, int out_size) {
    const float* q    = (const float*)d_in[0];
    const float* emb  = (const float*)d_in[1];
    const int*   info = (const int*)d_in[2];
    const int*   idxb = (const int*)d_in[3];
    const int*   idxr = (const int*)d_in[4];
    float* out = (float*)d_out;
    const int P = in_sizes[3];

    const int gemm_smem = (128 * 2 + 256 * 2) * PAD * (int)sizeof(__nv_bfloat16);
    const int gath_smem = BS_ * V_ * (int)sizeof(float);

    static int init_done = 0;
    if (!init_done) {
        cudaFuncSetAttribute(fused_run_kernel,
                             cudaFuncAttributeMaxDynamicSharedMemorySize,
                             SM_TOTAL);
        cudaFuncSetAttribute(gemm_fallback_kernel,
                             cudaFuncAttributeMaxDynamicSharedMemorySize,
                             gemm_smem);
        cudaFuncSetAttribute(gather_fallback_kernel,
                             cudaFuncAttributeMaxDynamicSharedMemorySize,
                             gath_smem);
        init_done = 1;
    }

    if (P == B_ * PPB_) {
        fused_run_kernel<<<B_ * R_, 1024, SM_TOTAL>>>(
            q, emb, info, idxb, idxr, out);
    } else {
        gemm_fallback_kernel<<<dim3(SEQ_ / 128, V_ / 256, B_), 256,
                               gemm_smem>>>(q, emb);
        gather_fallback_kernel<<<(P + 15) / 16, 256, gath_smem>>>(
            info, idxb, idxr, out, P);
    }
}